// round 11
// baseline (speedup 1.0000x reference)
#include <cuda_runtime.h>
#include <stdint.h>

// ============================================================================
// ImpulseNoise — bit-exact JAX (threefry_partitionable) salt & pepper.
// key=(0,42); k_flip = tf20(key,(0,0)); k_salt = tf20(key,(0,1))
// bits(i) = fold(tf20(k, (0, i)));  u = (bits>>9)*2^-23
// u <= 0.09f  <=>  bits <= (754974<<9)|511     (rel_err=0 verified R2-R10)
// u <= 0.5    <=>  bits <= 0x800001FF
//
// R11 = R10 (4 injection folds -> 66 instr/hash; k=8 IMAD.WIDE rotates ->
//       alu ~37 ops/hash) + __launch_bounds__(256, 8) pinning regs<=32.
// R10 measured: stream-units 127->122 (folds worked) but regs=40 dropped
// occ to 68% and issue to 71%. R7 proved this exact config class holds
// regs=32 / occ 92% under launch_bounds(256,8) without spills.
// Salt hashes remain warp-ballot-compacted (~0.09 hashes/elem).
// ============================================================================

struct U2c { unsigned a, b; };

constexpr U2c threefry20_host(unsigned k0, unsigned k1, unsigned x0, unsigned x1) {
    unsigned ks2 = k0 ^ k1 ^ 0x1BD11BDAu;
    x0 += k0; x1 += k1;
#define TFR_H(r) { x0 += x1; x1 = (x1 << (r)) | (x1 >> (32 - (r))); x1 ^= x0; }
    TFR_H(13) TFR_H(15) TFR_H(26) TFR_H(6)
    x0 += k1;  x1 += ks2 + 1u;
    TFR_H(17) TFR_H(29) TFR_H(16) TFR_H(24)
    x0 += ks2; x1 += k0 + 2u;
    TFR_H(13) TFR_H(15) TFR_H(26) TFR_H(6)
    x0 += k0;  x1 += k1 + 3u;
    TFR_H(17) TFR_H(29) TFR_H(16) TFR_H(24)
    x0 += k1;  x1 += ks2 + 4u;
    TFR_H(13) TFR_H(15) TFR_H(26) TFR_H(6)
    x0 += ks2; x1 += k0 + 5u;
#undef TFR_H
    return U2c{x0, x1};
}

constexpr U2c KFLIP = threefry20_host(0u, 42u, 0u, 0u);
constexpr U2c KSALT = threefry20_host(0u, 42u, 0u, 1u);

constexpr unsigned N_TOTAL = 64u * 3u * 512u * 512u;   // 50331648
constexpr unsigned FLIP_T  = (754974u << 9) | 511u;    // u <= 0.09f
constexpr unsigned SALT_T  = 0x800001FFu;              // u <= 0.5f

// Adds forced to IMAD (fma pipe): d = a*one + b.
__device__ __forceinline__ unsigned madr(unsigned a, unsigned one, unsigned b) {
    unsigned d;
    asm("mad.lo.u32 %0, %1, %2, %3;" : "=r"(d) : "r"(a), "r"(one), "r"(b));
    return d;
}
template <unsigned IMM>
__device__ __forceinline__ unsigned madi(unsigned a, unsigned one) {
    unsigned d;
    asm("mad.lo.u32 %0, %1, %2, %3;" : "=r"(d) : "r"(a), "r"(one), "n"(IMM));
    return d;
}

// SHF round: add on fma, rot+xor on alu.
#define TFR_S(r) { x0 = madr(x0, one, x1); x1 = __funnelshift_l(x1, x1, (r)); x1 ^= x0; }
// WIDE round: add on fma, rotate via IMAD.WIDE (fma), (lo|hi)^x0 = one LOP3 (alu).
#define TFR_W(mr) { x0 = madr(x0, one, x1);                                    \
    unsigned long long p = (unsigned long long)x1 * (unsigned long long)(mr);   \
    x1 = ((unsigned)p | (unsigned)(p >> 32)) ^ x0; }
// Injection-folded SHF round: x1 takes its constant (IMAD), x0's injection is
// absorbed into the round add as ONE 3-input IADD3: x0 = x0 + x1 + C0.
#define TFR_INJ(C1, C0, r) {                         \
    x1 = madi<(C1)>(x1, one);                         \
    x0 = x0 + x1 + (C0);                              \
    x1 = __funnelshift_l(x1, x1, (r)); x1 ^= x0; }

// Threefry-2x32-20, counter (0, i), returns x0^x1.
// Wide rounds: 2,3,6,10,11,14,18,19 (rot 15,26,29,15,26,29,15,26).
template <unsigned K0, unsigned K1>
__device__ __forceinline__ unsigned tf20_fold(unsigned i, unsigned one,
                                              unsigned m15, unsigned m26,
                                              unsigned m29) {
    constexpr unsigned KS2 = K0 ^ K1 ^ 0x1BD11BDAu;
    unsigned x1 = madi<K1>(i, one);
    unsigned x0 = madi<K0>(x1, one);                 // round-1 add (x0_init=K0)
    x1 = __funnelshift_l(x1, x1, 13); x1 ^= x0;      // finish round 1 (SHF)
    TFR_W(m15) TFR_W(m26) TFR_S(6)                   // rounds 2,3,4
    TFR_INJ(KS2 + 1u, K1, 17)                        // inj1 + round 5
    TFR_W(m29) TFR_S(16) TFR_S(24)                   // rounds 6,7,8
    TFR_INJ(K0 + 2u, KS2, 13)                        // inj2 + round 9
    TFR_W(m15) TFR_W(m26) TFR_S(6)                   // rounds 10,11,12
    TFR_INJ(K1 + 3u, K0, 17)                         // inj3 + round 13
    TFR_W(m29) TFR_S(16) TFR_S(24)                   // rounds 14,15,16
    TFR_INJ(KS2 + 4u, K1, 13)                        // inj4 + round 17
    TFR_W(m15) TFR_W(m26) TFR_S(6)                   // rounds 18,19,20
    // final injection folded into the output fold:
    return (x0 + KS2) ^ (x1 + (K0 + 5u));
}
#undef TFR_S
#undef TFR_W
#undef TFR_INJ

// 8 elements per thread; warp covers 256 consecutive elements.
// launch_bounds(256, 8): pin regs<=32 (R7-proven safe for wide-rotate kernels).
__global__ void __launch_bounds__(256, 8)
impulse_noise_kernel(const float* __restrict__ img, float* __restrict__ out,
                     unsigned one) {
    unsigned m15 = one << 15, m26 = one << 26, m29 = one << 29;

    unsigned gwarp = (blockIdx.x * 256u + threadIdx.x) >> 5;
    unsigned lane  = threadIdx.x & 31u;
    unsigned base  = gwarp * 256u;
    unsigned i0 = base + 4u * lane;
    unsigned i1 = base + 128u + 4u * lane;

    float4 v0 = *reinterpret_cast<const float4*>(img + i0);
    float4 v1 = *reinterpret_cast<const float4*>(img + i1);

    // Mandatory flip hashes (8 independent chains for ILP).
    bool fl[8];
#pragma unroll
    for (int s = 0; s < 4; ++s)
        fl[s] = tf20_fold<KFLIP.a, KFLIP.b>(i0 + (unsigned)s, one, m15, m26, m29) <= FLIP_T;
#pragma unroll
    for (int s = 0; s < 4; ++s)
        fl[4 + s] = tf20_fold<KFLIP.a, KFLIP.b>(i1 + (unsigned)s, one, m15, m26, m29) <= FLIP_T;

    // Owners store raw values; flipped slots overwritten after the fence.
    *reinterpret_cast<float4*>(out + i0) = v0;
    *reinterpret_cast<float4*>(out + i1) = v1;

    // Warp-uniform flip masks + prefix counts.
    unsigned m[8], cum[9];
    cum[0] = 0;
#pragma unroll
    for (int s = 0; s < 8; ++s) {
        m[s] = __ballot_sync(0xFFFFFFFFu, fl[s]);
        cum[s + 1] = cum[s] + (unsigned)__popc(m[s]);
    }
    unsigned nf = cum[8];

    __syncwarp();  // owner stores happen-before compacted overwrites

    // Compacted salt passes: 32 flips served per pass (~1 pass typical).
    for (unsigned start = 0; start < nf; start += 32u) {
        unsigned r = start + lane;
        if (r < nf) {
            unsigned mm = m[0], rbase = 0u, eoff = 0u;
#pragma unroll
            for (int w = 1; w < 8; ++w) {
                if (r >= cum[w]) {
                    mm = m[w];
                    rbase = cum[w];
                    eoff = (w < 4) ? (unsigned)w : (unsigned)w + 124u;
                }
            }
            unsigned rr = r - rbase;
            unsigned pos = 0u, c;
            c = (unsigned)__popc(mm & 0xFFFFu); if (rr >= c) { rr -= c; pos += 16u; mm >>= 16; }
            c = (unsigned)__popc(mm & 0xFFu);   if (rr >= c) { rr -= c; pos += 8u;  mm >>= 8; }
            c = (unsigned)__popc(mm & 0xFu);    if (rr >= c) { rr -= c; pos += 4u;  mm >>= 4; }
            c = (unsigned)__popc(mm & 0x3u);    if (rr >= c) { rr -= c; pos += 2u;  mm >>= 2; }
            c = mm & 1u;                        if (rr >= c) { pos += 1u; }

            unsigned gi = base + 4u * pos + eoff;
            unsigned bs = tf20_fold<KSALT.a, KSALT.b>(gi, one, m15, m26, m29);
            out[gi] = (bs <= SALT_T) ? 1.0f : 0.0f;
        }
    }
}

extern "C" void kernel_launch(void* const* d_in, const int* in_sizes, int n_in,
                              void* d_out, int out_size) {
    const float* img = (const float*)d_in[0];
    float* out = (float*)d_out;
    constexpr unsigned threads = N_TOTAL / 8u;    // 6291456
    constexpr unsigned blocks  = threads / 256u;  // 24576
    impulse_noise_kernel<<<blocks, 256>>>(img, out, 1u);
}

// round 12
// speedup vs baseline: 1.0715x; 1.0715x over previous
#include <cuda_runtime.h>
#include <stdint.h>

// ============================================================================
// ImpulseNoise — bit-exact JAX (threefry_partitionable) salt & pepper.
// key=(0,42); k_flip = tf20(key,(0,0)); k_salt = tf20(key,(0,1))
// bits(i) = fold(tf20(k, (0, i)));  u = (bits>>9)*2^-23
// u <= 0.09f  <=>  bits <= (754974<<9)|511     (rel_err=0 verified R2-R11)
// u <= 0.5    <=>  bits <= 0x800001FF
//
// R12 = R4 (best: 159.3us, alu-time-bound at 86 SMSP-cyc/hash) with FIVE
// rotates converted to the mullo/mulhi form:
//    rotl(x,r) = (x*2^r) | __umulhi(x,2^r)   -> 2 single-reg IMADs (fma)
//    round combine (lo|hi)^x0                -> ONE fused LOP3 (alu)
// Unlike IMAD.WIDE (R5/R7/R10/R11: pair writeback poisoned issue to ~71%
// INDEPENDENT of occupancy), both muls are single-register rt=2 fma ops
// issuing in parallel — same 8-cyc round depth as SHF->LOP3.
// k=5 balances: alu-time 100.6 -> ~89.5 cyc/elem ~= fma-time.
// Converted rounds: 2,6,10,14,18 (rot 15,29,15,29,15; two multiplier regs).
// Salt hashes remain warp-ballot-compacted (~0.09 hashes/elem).
// ============================================================================

struct U2c { unsigned a, b; };

constexpr U2c threefry20_host(unsigned k0, unsigned k1, unsigned x0, unsigned x1) {
    unsigned ks2 = k0 ^ k1 ^ 0x1BD11BDAu;
    x0 += k0; x1 += k1;
#define TFR_H(r) { x0 += x1; x1 = (x1 << (r)) | (x1 >> (32 - (r))); x1 ^= x0; }
    TFR_H(13) TFR_H(15) TFR_H(26) TFR_H(6)
    x0 += k1;  x1 += ks2 + 1u;
    TFR_H(17) TFR_H(29) TFR_H(16) TFR_H(24)
    x0 += ks2; x1 += k0 + 2u;
    TFR_H(13) TFR_H(15) TFR_H(26) TFR_H(6)
    x0 += k0;  x1 += k1 + 3u;
    TFR_H(17) TFR_H(29) TFR_H(16) TFR_H(24)
    x0 += k1;  x1 += ks2 + 4u;
    TFR_H(13) TFR_H(15) TFR_H(26) TFR_H(6)
    x0 += ks2; x1 += k0 + 5u;
#undef TFR_H
    return U2c{x0, x1};
}

constexpr U2c KFLIP = threefry20_host(0u, 42u, 0u, 0u);
constexpr U2c KSALT = threefry20_host(0u, 42u, 0u, 1u);

constexpr unsigned N_TOTAL = 64u * 3u * 512u * 512u;   // 50331648
constexpr unsigned FLIP_T  = (754974u << 9) | 511u;    // u <= 0.09f
constexpr unsigned SALT_T  = 0x800001FFu;              // u <= 0.5f

// Adds forced to IMAD (fma pipe): d = a*one + b  (R4-proven).
__device__ __forceinline__ unsigned madr(unsigned a, unsigned one, unsigned b) {
    unsigned d;
    asm("mad.lo.u32 %0, %1, %2, %3;" : "=r"(d) : "r"(a), "r"(one), "r"(b));
    return d;
}
template <unsigned IMM>
__device__ __forceinline__ unsigned madi(unsigned a, unsigned one) {
    unsigned d;
    asm("mad.lo.u32 %0, %1, %2, %3;" : "=r"(d) : "r"(a), "r"(one), "n"(IMM));
    return d;
}

// SHF round: add (fma) + SHF (alu) + LOP3 (alu).
#define TFR_S(r) { x0 = madr(x0, one, x1); x1 = __funnelshift_l(x1, x1, (r)); x1 ^= x0; }
// MUL-PAIR round: add (fma) + mullo,mulhi (2x single-reg IMAD, fma, parallel)
// + fused (lo|hi)^x0 (ONE LOP3, alu).
#define TFR_M2(mr) { x0 = madr(x0, one, x1);            \
    unsigned lo = x1 * (mr);                             \
    unsigned hi = __umulhi(x1, (mr));                    \
    x1 = (lo | hi) ^ x0; }

// Threefry-2x32-20, counter (0, i), returns x0^x1.
// Mul-pair rounds: 2,6,10,14,18 (rot 15,29,15,29,15).
template <unsigned K0, unsigned K1>
__device__ __forceinline__ unsigned tf20_fold(unsigned i, unsigned one,
                                              unsigned m15, unsigned m29) {
    constexpr unsigned KS2 = K0 ^ K1 ^ 0x1BD11BDAu;
    unsigned x1 = madi<K1>(i, one);
    unsigned x0 = madi<K0>(x1, one);                 // round-1 add (x0_init=K0)
    x1 = __funnelshift_l(x1, x1, 13); x1 ^= x0;      // finish round 1 (SHF)
    TFR_M2(m15) TFR_S(26) TFR_S(6)                   // rounds 2,3,4
    x0 = madi<K1>(x0, one);   x1 = madi<KS2 + 1u>(x1, one);
    TFR_S(17) TFR_M2(m29) TFR_S(16) TFR_S(24)        // rounds 5,6,7,8
    x0 = madi<KS2>(x0, one);  x1 = madi<K0 + 2u>(x1, one);
    TFR_S(13) TFR_M2(m15) TFR_S(26) TFR_S(6)         // rounds 9,10,11,12
    x0 = madi<K0>(x0, one);   x1 = madi<K1 + 3u>(x1, one);
    TFR_S(17) TFR_M2(m29) TFR_S(16) TFR_S(24)        // rounds 13,14,15,16
    x0 = madi<K1>(x0, one);   x1 = madi<KS2 + 4u>(x1, one);
    TFR_S(13) TFR_M2(m15) TFR_S(26) TFR_S(6)         // rounds 17,18,19,20
    x0 = madi<KS2>(x0, one);  x1 = madi<K0 + 5u>(x1, one);
    return x0 ^ x1;
}
#undef TFR_S
#undef TFR_M2

// 8 elements per thread; warp covers 256 consecutive elements.
__global__ void __launch_bounds__(256)
impulse_noise_kernel(const float* __restrict__ img, float* __restrict__ out,
                     unsigned one) {
    unsigned m15 = one << 15, m29 = one << 29;   // opaque 2^r multipliers

    unsigned gwarp = (blockIdx.x * 256u + threadIdx.x) >> 5;
    unsigned lane  = threadIdx.x & 31u;
    unsigned base  = gwarp * 256u;
    unsigned i0 = base + 4u * lane;
    unsigned i1 = base + 128u + 4u * lane;

    float4 v0 = *reinterpret_cast<const float4*>(img + i0);
    float4 v1 = *reinterpret_cast<const float4*>(img + i1);

    // Owners store raw values early (frees v0/v1 registers for the chains);
    // flipped slots overwritten after the fence below.
    *reinterpret_cast<float4*>(out + i0) = v0;
    *reinterpret_cast<float4*>(out + i1) = v1;

    // Mandatory flip hashes (8 independent chains for ILP).
    bool fl[8];
#pragma unroll
    for (int s = 0; s < 4; ++s)
        fl[s] = tf20_fold<KFLIP.a, KFLIP.b>(i0 + (unsigned)s, one, m15, m29) <= FLIP_T;
#pragma unroll
    for (int s = 0; s < 4; ++s)
        fl[4 + s] = tf20_fold<KFLIP.a, KFLIP.b>(i1 + (unsigned)s, one, m15, m29) <= FLIP_T;

    // Warp-uniform flip masks + prefix counts.
    unsigned m[8], cum[9];
    cum[0] = 0;
#pragma unroll
    for (int s = 0; s < 8; ++s) {
        m[s] = __ballot_sync(0xFFFFFFFFu, fl[s]);
        cum[s + 1] = cum[s] + (unsigned)__popc(m[s]);
    }
    unsigned nf = cum[8];

    __syncwarp();  // owner stores happen-before compacted overwrites

    // Compacted salt passes: 32 flips served per pass (~1 pass typical).
    for (unsigned start = 0; start < nf; start += 32u) {
        unsigned r = start + lane;
        if (r < nf) {
            unsigned mm = m[0], rbase = 0u, eoff = 0u;
#pragma unroll
            for (int w = 1; w < 8; ++w) {
                if (r >= cum[w]) {
                    mm = m[w];
                    rbase = cum[w];
                    eoff = (w < 4) ? (unsigned)w : (unsigned)w + 124u;
                }
            }
            unsigned rr = r - rbase;
            unsigned pos = 0u, c;
            c = (unsigned)__popc(mm & 0xFFFFu); if (rr >= c) { rr -= c; pos += 16u; mm >>= 16; }
            c = (unsigned)__popc(mm & 0xFFu);   if (rr >= c) { rr -= c; pos += 8u;  mm >>= 8; }
            c = (unsigned)__popc(mm & 0xFu);    if (rr >= c) { rr -= c; pos += 4u;  mm >>= 4; }
            c = (unsigned)__popc(mm & 0x3u);    if (rr >= c) { rr -= c; pos += 2u;  mm >>= 2; }
            c = mm & 1u;                        if (rr >= c) { pos += 1u; }

            unsigned gi = base + 4u * pos + eoff;
            unsigned bs = tf20_fold<KSALT.a, KSALT.b>(gi, one, m15, m29);
            out[gi] = (bs <= SALT_T) ? 1.0f : 0.0f;
        }
    }
}

extern "C" void kernel_launch(void* const* d_in, const int* in_sizes, int n_in,
                              void* d_out, int out_size) {
    const float* img = (const float*)d_in[0];
    float* out = (float*)d_out;
    constexpr unsigned threads = N_TOTAL / 8u;    // 6291456
    constexpr unsigned blocks  = threads / 256u;  // 24576
    impulse_noise_kernel<<<blocks, 256>>>(img, out, 1u);
}

// round 13
// speedup vs baseline: 1.1025x; 1.0289x over previous
#include <cuda_runtime.h>
#include <stdint.h>

// ============================================================================
// ImpulseNoise — bit-exact JAX (threefry_partitionable) salt & pepper.
// key=(0,42); k_flip = tf20(key,(0,0)); k_salt = tf20(key,(0,1))
// bits(i) = fold(tf20(k, (0, i)));  u = (bits>>9)*2^-23
// u <= 0.09f  <=>  bits <= (754974<<9)|511     (rel_err=0 verified R2-R12)
// u <= 0.5    <=>  bits <= 0x800001FF
//
// R13 = R4 champion (159.3us, alu-bound 89.6%) + two surgical changes:
//  (1) k=2 mul-pair rotates (rounds 6 & 14, rot 29 only -> ONE multiplier
//      reg). Sweep R4(k=0)/R12(k=5) brackets the optimum at k~2:
//      alu/hash 41->39 while stream grows just 74->76 (still alu-bound).
//  (2) counter-setup trim: hoist base+K1 out of the chain loops; each
//      hash's x1 init is ONE add instead of two (~1% stream).
// Salt hashes remain warp-ballot-compacted (~0.09 hashes/elem).
// ============================================================================

struct U2c { unsigned a, b; };

constexpr U2c threefry20_host(unsigned k0, unsigned k1, unsigned x0, unsigned x1) {
    unsigned ks2 = k0 ^ k1 ^ 0x1BD11BDAu;
    x0 += k0; x1 += k1;
#define TFR_H(r) { x0 += x1; x1 = (x1 << (r)) | (x1 >> (32 - (r))); x1 ^= x0; }
    TFR_H(13) TFR_H(15) TFR_H(26) TFR_H(6)
    x0 += k1;  x1 += ks2 + 1u;
    TFR_H(17) TFR_H(29) TFR_H(16) TFR_H(24)
    x0 += ks2; x1 += k0 + 2u;
    TFR_H(13) TFR_H(15) TFR_H(26) TFR_H(6)
    x0 += k0;  x1 += k1 + 3u;
    TFR_H(17) TFR_H(29) TFR_H(16) TFR_H(24)
    x0 += k1;  x1 += ks2 + 4u;
    TFR_H(13) TFR_H(15) TFR_H(26) TFR_H(6)
    x0 += ks2; x1 += k0 + 5u;
#undef TFR_H
    return U2c{x0, x1};
}

constexpr U2c KFLIP = threefry20_host(0u, 42u, 0u, 0u);
constexpr U2c KSALT = threefry20_host(0u, 42u, 0u, 1u);

constexpr unsigned N_TOTAL = 64u * 3u * 512u * 512u;   // 50331648
constexpr unsigned FLIP_T  = (754974u << 9) | 511u;    // u <= 0.09f
constexpr unsigned SALT_T  = 0x800001FFu;              // u <= 0.5f

// Adds forced to IMAD (fma pipe): d = a*one + b  (R4-proven placement).
__device__ __forceinline__ unsigned madr(unsigned a, unsigned one, unsigned b) {
    unsigned d;
    asm("mad.lo.u32 %0, %1, %2, %3;" : "=r"(d) : "r"(a), "r"(one), "r"(b));
    return d;
}
template <unsigned IMM>
__device__ __forceinline__ unsigned madi(unsigned a, unsigned one) {
    unsigned d;
    asm("mad.lo.u32 %0, %1, %2, %3;" : "=r"(d) : "r"(a), "r"(one), "n"(IMM));
    return d;
}

// SHF round: add (fma) + funnel-rotate (alu) + xor (alu).
#define TFR_S(r) { x0 = madr(x0, one, x1); x1 = __funnelshift_l(x1, x1, (r)); x1 ^= x0; }
// MUL-PAIR round: add (fma) + mullo,mulhi (2x single-reg IMAD, fma) +
// fused (lo|hi)^x0 (ONE LOP3, alu).
#define TFR_M2(mr) { x0 = madr(x0, one, x1);            \
    unsigned lo = x1 * (mr);                             \
    unsigned hi = __umulhi(x1, (mr));                    \
    x1 = (lo | hi) ^ x0; }

// Threefry-2x32-20 with x1 counter-init PRE-ADDED (x1in = i + K1).
// Mul-pair rounds: 6 and 14 (rot 29). Returns x0^x1.
template <unsigned K0, unsigned K1>
__device__ __forceinline__ unsigned tf20_fold_pre(unsigned x1in, unsigned one,
                                                  unsigned m29) {
    constexpr unsigned KS2 = K0 ^ K1 ^ 0x1BD11BDAu;
    unsigned x1 = x1in;
    unsigned x0 = madi<K0>(x1, one);                 // round-1 add (x0_init=K0)
    x1 = __funnelshift_l(x1, x1, 13); x1 ^= x0;      // finish round 1
    TFR_S(15) TFR_S(26) TFR_S(6)                     // rounds 2,3,4
    x0 = madi<K1>(x0, one);   x1 = madi<KS2 + 1u>(x1, one);
    TFR_S(17) TFR_M2(m29) TFR_S(16) TFR_S(24)        // rounds 5,6,7,8
    x0 = madi<KS2>(x0, one);  x1 = madi<K0 + 2u>(x1, one);
    TFR_S(13) TFR_S(15) TFR_S(26) TFR_S(6)           // rounds 9-12
    x0 = madi<K0>(x0, one);   x1 = madi<K1 + 3u>(x1, one);
    TFR_S(17) TFR_M2(m29) TFR_S(16) TFR_S(24)        // rounds 13,14,15,16
    x0 = madi<K1>(x0, one);   x1 = madi<KS2 + 4u>(x1, one);
    TFR_S(13) TFR_S(15) TFR_S(26) TFR_S(6)           // rounds 17-20
    x0 = madi<KS2>(x0, one);  x1 = madi<K0 + 5u>(x1, one);
    return x0 ^ x1;
}
#undef TFR_S
#undef TFR_M2

// 8 elements per thread; warp covers 256 consecutive elements.
__global__ void __launch_bounds__(256)
impulse_noise_kernel(const float* __restrict__ img, float* __restrict__ out,
                     unsigned one) {
    unsigned m29 = one << 29;   // opaque 2^29 multiplier

    unsigned gwarp = (blockIdx.x * 256u + threadIdx.x) >> 5;
    unsigned lane  = threadIdx.x & 31u;
    unsigned base  = gwarp * 256u;
    unsigned i0 = base + 4u * lane;
    unsigned i1 = base + 128u + 4u * lane;

    float4 v0 = *reinterpret_cast<const float4*>(img + i0);
    float4 v1 = *reinterpret_cast<const float4*>(img + i1);

    // Hoisted counter bases: each chain's x1 init is one add from these.
    unsigned b0f = madi<KFLIP.b>(i0, one);   // i0 + K1_flip
    unsigned b1f = madi<KFLIP.b>(i1, one);   // i1 + K1_flip

    // Mandatory flip hashes (8 independent chains for ILP).
    bool fl[8];
#pragma unroll
    for (int s = 0; s < 4; ++s)
        fl[s] = tf20_fold_pre<KFLIP.a, KFLIP.b>(b0f + (unsigned)s, one, m29) <= FLIP_T;
#pragma unroll
    for (int s = 0; s < 4; ++s)
        fl[4 + s] = tf20_fold_pre<KFLIP.a, KFLIP.b>(b1f + (unsigned)s, one, m29) <= FLIP_T;

    // Owners store raw values; flipped slots overwritten after the fence.
    *reinterpret_cast<float4*>(out + i0) = v0;
    *reinterpret_cast<float4*>(out + i1) = v1;

    // Warp-uniform flip masks + prefix counts.
    unsigned m[8], cum[9];
    cum[0] = 0;
#pragma unroll
    for (int s = 0; s < 8; ++s) {
        m[s] = __ballot_sync(0xFFFFFFFFu, fl[s]);
        cum[s + 1] = cum[s] + (unsigned)__popc(m[s]);
    }
    unsigned nf = cum[8];

    __syncwarp();  // owner stores happen-before compacted overwrites

    // Compacted salt passes: 32 flips served per pass (~1 pass typical).
    for (unsigned start = 0; start < nf; start += 32u) {
        unsigned r = start + lane;
        if (r < nf) {
            unsigned mm = m[0], rbase = 0u, eoff = 0u;
#pragma unroll
            for (int w = 1; w < 8; ++w) {
                if (r >= cum[w]) {
                    mm = m[w];
                    rbase = cum[w];
                    eoff = (w < 4) ? (unsigned)w : (unsigned)w + 124u;
                }
            }
            unsigned rr = r - rbase;
            unsigned pos = 0u, c;
            c = (unsigned)__popc(mm & 0xFFFFu); if (rr >= c) { rr -= c; pos += 16u; mm >>= 16; }
            c = (unsigned)__popc(mm & 0xFFu);   if (rr >= c) { rr -= c; pos += 8u;  mm >>= 8; }
            c = (unsigned)__popc(mm & 0xFu);    if (rr >= c) { rr -= c; pos += 4u;  mm >>= 4; }
            c = (unsigned)__popc(mm & 0x3u);    if (rr >= c) { rr -= c; pos += 2u;  mm >>= 2; }
            c = mm & 1u;                        if (rr >= c) { pos += 1u; }

            unsigned gi = base + 4u * pos + eoff;
            unsigned bs = tf20_fold_pre<KSALT.a, KSALT.b>(
                madi<KSALT.b>(gi, one), one, m29);
            out[gi] = (bs <= SALT_T) ? 1.0f : 0.0f;
        }
    }
}

extern "C" void kernel_launch(void* const* d_in, const int* in_sizes, int n_in,
                              void* d_out, int out_size) {
    const float* img = (const float*)d_in[0];
    float* out = (float*)d_out;
    constexpr unsigned threads = N_TOTAL / 8u;    // 6291456
    constexpr unsigned blocks  = threads / 256u;  // 24576
    impulse_noise_kernel<<<blocks, 256>>>(img, out, 1u);
}